// round 15
// baseline (speedup 1.0000x reference)
#include <cuda_runtime.h>
#include <cuda_bf16.h>
#include <cuda_fp8.h>
#include <cfloat>
#include <climits>
#include <cstdint>

// ---------------------------------------------------------------------------
// Problem shape (fixed):
//   query [B=256,1024] f32, bank [M=200000,1024] f32, traj [M,8,3] f32, k=16
// Output: traj[nn_idx] sorted by ascending L2 dist, ties -> lower index.
// Pipeline:
//   convert (fp32 -> e4m3, fused bsq) -> sample mini-GEMM -> threshold ->
//   main FP8 GEMM with fused threshold-filter epilogue ->
//   exact top-64 of surviving keys -> exact fp32 rescore -> top-16 -> gather.
// ---------------------------------------------------------------------------

#define C_DIM   1024
#define B_MAX   256
#define M_MAX   200000
#define KSEL    16
#define NCAND   64
#define CAP     4096                 // per-query filtered-key capacity
#define SAMPLE_TILES 26
#define SAMPLE_N (SAMPLE_TILES * 128)  // 3328 sampled bank rows
#define THR_RANK 8                   // take 8th smallest of sample

// __device__ scratch (allocation-free rule)
__device__ __align__(16) float          g_sample[(size_t)B_MAX * SAMPLE_N];
__device__ __align__(16) float          g_bsq[M_MAX];
__device__ __align__(16) uint8_t        g_bank_f8[(size_t)M_MAX * C_DIM];
__device__ __align__(16) uint8_t        g_q_f8[(size_t)B_MAX * C_DIM];
__device__ __align__(16) unsigned long long g_list[(size_t)B_MAX * CAP];
__device__                int           g_count[B_MAX];
__device__                float         g_thresh[B_MAX];
__device__                int           g_cand[B_MAX * NCAND];

#define SMEM_SWIZZLE_128B(o) ((o) ^ (((o) >> 3) & 0x70))

__device__ __forceinline__ uint32_t smem_to_u32(const void* p) {
    uint32_t a;
    asm("{ .reg .u64 t; cvta.to.shared.u64 t, %1; cvt.u32.u64 %0, t; }"
        : "=r"(a) : "l"(p));
    return a;
}
__device__ __forceinline__ void cp_async16(uint32_t dst, const void* src, int srcsize) {
    asm volatile("cp.async.cg.shared.global [%0], [%1], 16, %2;"
                 :: "r"(dst), "l"(src), "r"(srcsize));
}
__device__ __forceinline__ void cp_commit() {
    asm volatile("cp.async.commit_group;");
}
template <int N>
__device__ __forceinline__ void cp_wait() {
    asm volatile("cp.async.wait_group %0;" :: "n"(N));
}
__device__ __forceinline__ void ldmx4(uint32_t& r0, uint32_t& r1,
                                      uint32_t& r2, uint32_t& r3, uint32_t addr) {
    asm volatile("ldmatrix.sync.aligned.m8n8.x4.shared.b16 {%0,%1,%2,%3}, [%4];"
                 : "=r"(r0), "=r"(r1), "=r"(r2), "=r"(r3) : "r"(addr));
}
// FP8 e4m3 MMA: D[16x8] += A[16x32] * B[8x32]^T, fp32 accum.
__device__ __forceinline__ void mma16832f8(float* c, const uint32_t* a, const uint32_t* b) {
    asm volatile(
        "mma.sync.aligned.m16n8k32.row.col.f32.e4m3.e4m3.f32 "
        "{%0,%1,%2,%3}, {%4,%5,%6,%7}, {%8,%9}, {%0,%1,%2,%3};"
        : "+f"(c[0]), "+f"(c[1]), "+f"(c[2]), "+f"(c[3])
        : "r"(a[0]), "r"(a[1]), "r"(a[2]), "r"(a[3]), "r"(b[0]), "r"(b[1]));
}

// ---------------------------------------------------------------------------
// Selection key packing
// ---------------------------------------------------------------------------
__device__ __forceinline__ unsigned long long pack_key(float s, int idx) {
    unsigned u = __float_as_uint(s);
    u = (u & 0x80000000u) ? ~u : (u | 0x80000000u);
    return ((unsigned long long)u << 32) | (unsigned)idx;
}
__device__ __forceinline__ float unpack_score(unsigned long long key) {
    unsigned u = (unsigned)(key >> 32);
    u = (u & 0x80000000u) ? (u & 0x7fffffffu) : ~u;
    return __uint_as_float(u);
}
__device__ __forceinline__ unsigned long long warp_min_ull(unsigned long long v) {
#pragma unroll
    for (int off = 16; off > 0; off >>= 1) {
        unsigned long long o = __shfl_xor_sync(0xffffffffu, v, off);
        v = (o < v) ? o : v;
    }
    return v;
}

// ---------------------------------------------------------------------------
// Kernel 1: fp32 -> e4m3 convert, fused squared norms. One warp per row.
// ---------------------------------------------------------------------------
__global__ void convert_kernel(const float* __restrict__ src,
                               uint8_t* __restrict__ dst,
                               float* __restrict__ bsq, int rows) {
    int warp = (blockIdx.x * blockDim.x + threadIdx.x) >> 5;
    int lane = threadIdx.x & 31;
    if (warp >= rows) return;
    const float4* srow = reinterpret_cast<const float4*>(src + (size_t)warp * C_DIM);
    uint32_t* drow = reinterpret_cast<uint32_t*>(dst + (size_t)warp * C_DIM);
    float acc = 0.f;
#pragma unroll
    for (int i = 0; i < C_DIM / 128; i++) {
        int j = i * 32 + lane;            // float4 index 0..255
        float4 v = srow[j];
        acc += v.x * v.x + v.y * v.y + v.z * v.z + v.w * v.w;
        uint32_t b0 = __nv_cvt_float_to_fp8(v.x, __NV_SATFINITE, __NV_E4M3);
        uint32_t b1 = __nv_cvt_float_to_fp8(v.y, __NV_SATFINITE, __NV_E4M3);
        uint32_t b2 = __nv_cvt_float_to_fp8(v.z, __NV_SATFINITE, __NV_E4M3);
        uint32_t b3 = __nv_cvt_float_to_fp8(v.w, __NV_SATFINITE, __NV_E4M3);
        drow[j] = b0 | (b1 << 8) | (b2 << 16) | (b3 << 24);
    }
    if (bsq) {
#pragma unroll
        for (int off = 16; off > 0; off >>= 1)
            acc += __shfl_xor_sync(0xffffffffu, acc, off);
        if (lane == 0) bsq[warp] = acc;
    }
}

// ---------------------------------------------------------------------------
// Kernel 2: FP8 e4m3 GEMM via mma.sync.m16n8k32 with two epilogue modes:
//   mode 0 (sample): write scores to g_sample [B x SAMPLE_N]
//   mode 1 (filter): append keys with score <= g_thresh[q] to g_list
// K chunk = 128 fp8 elems = 128B rows (SW128). 8 chunks. 4 k32-steps/chunk.
// Fragment byte layout identical to bf16 m16n8k16 (b16-ldmatrix trick).
// ---------------------------------------------------------------------------
#define BM   128
#define BN   128
#define BKC  128                     // fp8 elems per K chunk (128 bytes)
#define NCH  (C_DIM / BKC)           // 8
#define TILE_BYTES (BM * 128)        // 16 KB per operand tile
#define GEMM_SMEM  (4 * TILE_BYTES)  // 64 KB

__global__ __launch_bounds__(256, 2)
void mma_gemm_kernel(int M, int mode) {
    extern __shared__ char smem[];
    const uint32_t sb = smem_to_u32(smem);
    const int tid  = threadIdx.x;
    const int wid  = tid >> 5;
    const int lane = tid & 31;
    const int qt = blockIdx.x;
    const int bn = blockIdx.y * BN;
    const int warp_m = wid & 1;
    const int warp_n = wid >> 1;

    const uint8_t* Abase = g_q_f8 + (size_t)qt * BM * C_DIM;

    int lrow[4], lu[4];
#pragma unroll
    for (int l = 0; l < 4; l++) {
        int id = tid + l * 256;           // 0..1023
        lrow[l] = id >> 3;                // row 0..127
        lu[l]   = id & 7;                 // 16B unit within 128B row
    }

    auto issue_loads = [&](int c, int buf) {
        int k0 = c * BKC;                 // byte == elem offset (1B/elem)
        uint32_t As = sb + buf * 2 * TILE_BYTES;
        uint32_t Bs = As + TILE_BYTES;
#pragma unroll
        for (int l = 0; l < 4; l++) {
            uint32_t so = SMEM_SWIZZLE_128B((uint32_t)(lrow[l] * 128 + lu[l] * 16));
            cp_async16(As + so, Abase + (size_t)lrow[l] * C_DIM + k0 + lu[l] * 16, 16);
            int n = bn + lrow[l];
            const void* srcB = g_bank_f8 + (size_t)(n < M ? n : 0) * C_DIM + k0 + lu[l] * 16;
            cp_async16(Bs + so, srcB, n < M ? 16 : 0);
        }
        cp_commit();
    };

    float acc[4][4][4];
#pragma unroll
    for (int mi = 0; mi < 4; mi++)
#pragma unroll
        for (int nj = 0; nj < 4; nj++)
#pragma unroll
            for (int e = 0; e < 4; e++) acc[mi][nj][e] = 0.f;

    issue_loads(0, 0);

    for (int c = 0; c < NCH; c++) {
        int buf = c & 1;
        if (c + 1 < NCH) {
            issue_loads(c + 1, buf ^ 1);
            cp_wait<1>();
        } else {
            cp_wait<0>();
        }
        __syncthreads();

        uint32_t As = sb + buf * 2 * TILE_BYTES;
        uint32_t Bs = As + TILE_BYTES;
#pragma unroll
        for (int ks = 0; ks < BKC / 32; ks++) {        // 4 k32-steps
            uint32_t a[4][4];
            int arow  = warp_m * 64 + (lane & 15);
            int abyte = ks * 32 + (lane >> 4) * 16;
#pragma unroll
            for (int mi = 0; mi < 4; mi++) {
                uint32_t so = SMEM_SWIZZLE_128B(
                    (uint32_t)((arow + mi * 16) * 128 + abyte));
                ldmx4(a[mi][0], a[mi][1], a[mi][2], a[mi][3], As + so);
            }
            uint32_t b[4][2];
            int g = lane >> 3;
#pragma unroll
            for (int pair = 0; pair < 2; pair++) {
                int brow  = warp_n * 32 + pair * 16 + ((g >> 1) & 1) * 8 + (lane & 7);
                int bbyte = ks * 32 + (g & 1) * 16;
                uint32_t so = SMEM_SWIZZLE_128B((uint32_t)(brow * 128 + bbyte));
                uint32_t r0, r1, r2, r3;
                ldmx4(r0, r1, r2, r3, Bs + so);
                b[2 * pair][0] = r0; b[2 * pair][1] = r1;
                b[2 * pair + 1][0] = r2; b[2 * pair + 1][1] = r3;
            }
#pragma unroll
            for (int mi = 0; mi < 4; mi++)
#pragma unroll
                for (int nj = 0; nj < 4; nj++)
                    mma16832f8(acc[mi][nj], a[mi], b[nj]);
        }
        __syncthreads();
    }

    const int qbase = qt * BM + warp_m * 64;
    const int nbase = bn + warp_n * 32;

    if (mode == 0) {
        // sample epilogue: write scores into g_sample (row stride SAMPLE_N)
#pragma unroll
        for (int mi = 0; mi < 4; mi++) {
            int q0 = qbase + mi * 16 + (lane >> 2);
#pragma unroll
            for (int nj = 0; nj < 4; nj++) {
                int n0 = nbase + nj * 8 + (lane & 3) * 2;
                float b0 = g_bsq[n0], b1 = g_bsq[n0 + 1];
                float2 v0 = make_float2(b0 - 2.f * acc[mi][nj][0],
                                        b1 - 2.f * acc[mi][nj][1]);
                float2 v1 = make_float2(b0 - 2.f * acc[mi][nj][2],
                                        b1 - 2.f * acc[mi][nj][3]);
                *reinterpret_cast<float2*>(g_sample + (size_t)q0 * SAMPLE_N + n0) = v0;
                *reinterpret_cast<float2*>(g_sample + (size_t)(q0 + 8) * SAMPLE_N + n0) = v1;
            }
        }
    } else {
        // filter epilogue: append survivors (score <= per-query threshold)
#pragma unroll
        for (int mi = 0; mi < 4; mi++) {
            int q0 = qbase + mi * 16 + (lane >> 2);
            int q1 = q0 + 8;
            float T0 = g_thresh[q0];
            float T1 = g_thresh[q1];
#pragma unroll
            for (int nj = 0; nj < 4; nj++) {
                int n0 = nbase + nj * 8 + (lane & 3) * 2;
                if (n0 < M) {
                    float b0 = g_bsq[n0];
                    float s00 = b0 - 2.f * acc[mi][nj][0];
                    float s10 = b0 - 2.f * acc[mi][nj][2];
                    if (s00 <= T0) {
                        int pos = atomicAdd(&g_count[q0], 1);
                        if (pos < CAP) g_list[(size_t)q0 * CAP + pos] = pack_key(s00, n0);
                    }
                    if (s10 <= T1) {
                        int pos = atomicAdd(&g_count[q1], 1);
                        if (pos < CAP) g_list[(size_t)q1 * CAP + pos] = pack_key(s10, n0);
                    }
                    if (n0 + 1 < M) {
                        float b1 = g_bsq[n0 + 1];
                        float s01 = b1 - 2.f * acc[mi][nj][1];
                        float s11 = b1 - 2.f * acc[mi][nj][3];
                        if (s01 <= T0) {
                            int pos = atomicAdd(&g_count[q0], 1);
                            if (pos < CAP) g_list[(size_t)q0 * CAP + pos] = pack_key(s01, n0 + 1);
                        }
                        if (s11 <= T1) {
                            int pos = atomicAdd(&g_count[q1], 1);
                            if (pos < CAP) g_list[(size_t)q1 * CAP + pos] = pack_key(s11, n0 + 1);
                        }
                    }
                }
            }
        }
    }
}

// ---------------------------------------------------------------------------
// Kernel 3: per-query threshold = THR_RANK-th smallest of the sample row.
// ---------------------------------------------------------------------------
__global__ __launch_bounds__(256)
void sample_thresh_kernel() {
    const int q    = blockIdx.x;
    const int tid  = threadIdx.x;
    const int wid  = tid >> 5;
    const int lane = tid & 31;
    const float4* row4 = reinterpret_cast<const float4*>(g_sample + (size_t)q * SAMPLE_N);
    const int N4 = SAMPLE_N / 4;             // 832
    __shared__ unsigned long long wkeys[64];

    float ls[THR_RANK];
#pragma unroll
    for (int j = 0; j < THR_RANK; j++) ls[j] = FLT_MAX;
    const int per_warp = (N4 + 7) / 8;       // 104
    const int j0 = wid * per_warp;
    const int j1 = min(N4, j0 + per_warp);
    for (int j4 = j0 + lane; j4 < j1; j4 += 32) {
        float4 v = row4[j4];
        float e[4] = {v.x, v.y, v.z, v.w};
#pragma unroll
        for (int t = 0; t < 4; t++) {
            float cs = e[t];
            if (cs < ls[THR_RANK - 1]) {
#pragma unroll
                for (int j = 0; j < THR_RANK; j++) {
                    if (cs < ls[j]) { float ts = ls[j]; ls[j] = cs; cs = ts; }
                }
            }
        }
    }
    unsigned long long kk[THR_RANK];
#pragma unroll
    for (int j = 0; j < THR_RANK; j++) kk[j] = pack_key(ls[j], (wid << 8) | (lane << 3) | j);
    unsigned long long mine = ~0ull;
#pragma unroll
    for (int r = 0; r < THR_RANK; r++) {
        unsigned long long best = warp_min_ull(kk[0]);
        if (kk[0] == best) {
#pragma unroll
            for (int j = 0; j < THR_RANK - 1; j++) kk[j] = kk[j + 1];
            kk[THR_RANK - 1] = ~0ull;
        }
        if (lane == r) mine = best;
    }
    if (lane < THR_RANK) wkeys[wid * THR_RANK + lane] = mine;
    __syncthreads();

    if (wid == 0) {
        unsigned long long p0 = wkeys[lane], p1 = wkeys[32 + lane];
        if (p1 < p0) { unsigned long long t = p0; p0 = p1; p1 = t; }
        unsigned long long best = 0;
#pragma unroll
        for (int r = 0; r < THR_RANK; r++) {
            best = warp_min_ull(p0);
            if (p0 == best) { p0 = p1; p1 = ~0ull; }
        }
        if (lane == 0) {
            g_thresh[q] = unpack_score(best);
            g_count[q]  = 0;
        }
    }
}

// ---------------------------------------------------------------------------
// Kernel 4: per-query exact top-64 of the filtered keys.
// ---------------------------------------------------------------------------
__global__ __launch_bounds__(256)
void merge_cand_kernel() {
    const int q    = blockIdx.x;
    const int tid  = threadIdx.x;
    const int wid  = tid >> 5;
    const int lane = tid & 31;
    const int n    = min(g_count[q], CAP);
    const unsigned long long* list = g_list + (size_t)q * CAP;
    __shared__ unsigned long long keys[256];

    unsigned long long kk[8];
#pragma unroll
    for (int j = 0; j < 8; j++) kk[j] = ~0ull;
    for (int t = tid; t < n; t += 256) {
        unsigned long long ck = list[t];
        if (ck < kk[7]) {
#pragma unroll
            for (int j = 0; j < 8; j++) {
                if (ck < kk[j]) { unsigned long long tk = kk[j]; kk[j] = ck; ck = tk; }
            }
        }
    }

    unsigned long long mine = ~0ull;
#pragma unroll
    for (int r = 0; r < 32; r++) {
        unsigned long long best = warp_min_ull(kk[0]);
        if (kk[0] == best && best != ~0ull) {
#pragma unroll
            for (int j = 0; j < 7; j++) kk[j] = kk[j + 1];
            kk[7] = ~0ull;
        }
        if (lane == r) mine = best;
    }
    keys[wid * 32 + lane] = mine;
    __syncthreads();

    for (int k = 2; k <= 256; k <<= 1) {
        for (int j = k >> 1; j > 0; j >>= 1) {
            int ixj = tid ^ j;
            if (ixj > tid) {
                unsigned long long a = keys[tid], b = keys[ixj];
                bool up = ((tid & k) == 0);
                if ((a > b) == up) { keys[tid] = b; keys[ixj] = a; }
            }
            __syncthreads();
        }
    }
    if (tid < NCAND) {
        unsigned long long kv = keys[tid];
        g_cand[q * NCAND + tid] = (kv == ~0ull) ? 0 : (int)(kv & 0xffffffffu);
    }
}

// ---------------------------------------------------------------------------
// Kernel 5: exact fp32 rescore of 64 candidates, top-16, gather trajectories.
// ---------------------------------------------------------------------------
__global__ __launch_bounds__(256)
void rescore_gather_kernel(const float* __restrict__ Q,
                           const float* __restrict__ Bank,
                           const float* __restrict__ traj,
                           float* __restrict__ out, int TD) {
    const int q   = blockIdx.x;
    const int tid = threadIdx.x;
    const int wid = tid >> 5, lane = tid & 31;

    __shared__ __align__(16) float qrow[C_DIM];
    __shared__ float cs[NCAND];
    __shared__ int   ci[NCAND];
    __shared__ unsigned long long k64[NCAND];

    for (int t = tid; t < C_DIM; t += 256)
        qrow[t] = Q[(size_t)q * C_DIM + t];
    __syncthreads();

    const float4* q4 = reinterpret_cast<const float4*>(qrow);
    for (int cand = wid; cand < NCAND; cand += 8) {
        int idx = g_cand[q * NCAND + cand];
        const float4* b4 = reinterpret_cast<const float4*>(Bank + (size_t)idx * C_DIM);
        float acc = 0.f;
#pragma unroll
        for (int j = lane; j < C_DIM / 4; j += 32) {
            float4 a = q4[j], b = b4[j];
            acc += a.x * b.x + a.y * b.y + a.z * b.z + a.w * b.w;
        }
#pragma unroll
        for (int off = 16; off > 0; off >>= 1)
            acc += __shfl_xor_sync(0xffffffffu, acc, off);
        if (lane == 0) { cs[cand] = g_bsq[idx] - 2.0f * acc; ci[cand] = idx; }
    }
    __syncthreads();

    if (tid < NCAND) k64[tid] = pack_key(cs[tid], ci[tid]);
    __syncthreads();
    for (int k = 2; k <= NCAND; k <<= 1) {
        for (int j = k >> 1; j > 0; j >>= 1) {
            for (int t = tid; t < NCAND; t += 256) {
                int ixj = t ^ j;
                if (ixj > t) {
                    unsigned long long a = k64[t], b = k64[ixj];
                    bool up = ((t & k) == 0);
                    if ((a > b) == up) { k64[t] = b; k64[ixj] = a; }
                }
            }
            __syncthreads();
        }
    }

    for (int t = tid; t < KSEL * TD; t += 256) {
        int r = t / TD;
        int c = t - r * TD;
        int idx = (int)(k64[r] & 0xffffffffu);
        out[(size_t)q * KSEL * TD + t] = traj[(size_t)idx * TD + c];
    }
}

// ---------------------------------------------------------------------------
// Launch
// ---------------------------------------------------------------------------
extern "C" void kernel_launch(void* const* d_in, const int* in_sizes, int n_in,
                              void* d_out, int out_size) {
    const float* Q    = (const float*)d_in[0];
    const float* Bank = (const float*)d_in[1];
    const float* Traj = (const float*)d_in[2];
    float* out = (float*)d_out;

    const int C  = C_DIM;
    const int B  = in_sizes[0] / C;    // 256
    const int M  = in_sizes[1] / C;    // 200000
    const int TD = in_sizes[2] / M;    // 24

    cudaFuncSetAttribute(mma_gemm_kernel,
                         cudaFuncAttributeMaxDynamicSharedMemorySize, GEMM_SMEM);

    float* bsq_p = nullptr;
    uint8_t *bankf8_p = nullptr, *qf8_p = nullptr;
    cudaGetSymbolAddress((void**)&bsq_p, g_bsq);
    cudaGetSymbolAddress((void**)&bankf8_p, g_bank_f8);
    cudaGetSymbolAddress((void**)&qf8_p, g_q_f8);

    // 1) convert bank (+bsq) and query to e4m3
    {
        int ctas = (M * 32 + 255) / 256;
        convert_kernel<<<ctas, 256>>>(Bank, bankf8_p, bsq_p, M);
        int qctas = (B * 32 + 255) / 256;
        convert_kernel<<<qctas, 256>>>(Q, qf8_p, nullptr, B);
    }
    // 2) sample mini-GEMM over first SAMPLE_N bank rows
    {
        dim3 grid(B / BM, SAMPLE_TILES);
        mma_gemm_kernel<<<grid, 256, GEMM_SMEM>>>(M, 0);
    }
    // 3) per-query threshold + counter reset
    sample_thresh_kernel<<<B, 256>>>();
    // 4) main FP8 GEMM with fused threshold-filter epilogue
    {
        dim3 grid(B / BM, (M + BN - 1) / BN);
        mma_gemm_kernel<<<grid, 256, GEMM_SMEM>>>(M, 1);
    }
    // 5) exact top-64 of filtered keys
    merge_cand_kernel<<<B, 256>>>();
    // 6) exact fp32 rescore + top-16 + gather
    rescore_gather_kernel<<<B, 256>>>(Q, Bank, Traj, out, TD);
}

// round 16
// speedup vs baseline: 1.1168x; 1.1168x over previous
#include <cuda_runtime.h>
#include <cuda_bf16.h>
#include <cfloat>
#include <climits>
#include <cstdint>

// ---------------------------------------------------------------------------
// Problem shape (fixed):
//   query [B=256,1024] f32, bank [M=200000,1024] f32, traj [M,8,3] f32, k=16
// Output: traj[nn_idx] sorted by ascending L2 dist, ties -> lower index.
// Pipeline:
//   query convert (tiny) -> sample mini-GEMM -> threshold ->
//   main bf16 GEMM with IN-KERNEL fp32->bf16 bank conversion + fused norm
//   accumulation + fused threshold-filter epilogue ->
//   exact top-64 of surviving keys -> exact fp32 rescore -> top-16 -> gather.
// No bank_bf array, no bsq array, no score array.
// ---------------------------------------------------------------------------

#define C_DIM   1024
#define B_MAX   256
#define M_MAX   200000
#define KSEL    16
#define NCAND   64
#define CAP     4096
#define SAMPLE_TILES 26
#define SAMPLE_N (SAMPLE_TILES * 128)  // 3328 sampled bank rows
#define THR_RANK 8

// __device__ scratch (allocation-free rule)
__device__ __align__(16) float          g_sample[(size_t)B_MAX * SAMPLE_N];
__device__ __align__(16) __nv_bfloat16  g_q_bf[(size_t)B_MAX * C_DIM];
__device__ __align__(16) unsigned long long g_list[(size_t)B_MAX * CAP];
__device__                int           g_count[B_MAX];
__device__                float         g_thresh[B_MAX];
__device__                int           g_cand[B_MAX * NCAND];

#define SMEM_SWIZZLE_128B(o) ((o) ^ (((o) >> 3) & 0x70))

__device__ __forceinline__ uint32_t smem_to_u32(const void* p) {
    uint32_t a;
    asm("{ .reg .u64 t; cvta.to.shared.u64 t, %1; cvt.u32.u64 %0, t; }"
        : "=r"(a) : "l"(p));
    return a;
}
__device__ __forceinline__ void cp_async16(uint32_t dst, const void* src, int srcsize) {
    asm volatile("cp.async.cg.shared.global [%0], [%1], 16, %2;"
                 :: "r"(dst), "l"(src), "r"(srcsize));
}
__device__ __forceinline__ void cp_commit() {
    asm volatile("cp.async.commit_group;");
}
template <int N>
__device__ __forceinline__ void cp_wait() {
    asm volatile("cp.async.wait_group %0;" :: "n"(N));
}
__device__ __forceinline__ void ldmx4(uint32_t& r0, uint32_t& r1,
                                      uint32_t& r2, uint32_t& r3, uint32_t addr) {
    asm volatile("ldmatrix.sync.aligned.m8n8.x4.shared.b16 {%0,%1,%2,%3}, [%4];"
                 : "=r"(r0), "=r"(r1), "=r"(r2), "=r"(r3) : "r"(addr));
}
__device__ __forceinline__ void mma16816(float* c, const uint32_t* a, const uint32_t* b) {
    asm volatile(
        "mma.sync.aligned.m16n8k16.row.col.f32.bf16.bf16.f32 "
        "{%0,%1,%2,%3}, {%4,%5,%6,%7}, {%8,%9}, {%0,%1,%2,%3};"
        : "+f"(c[0]), "+f"(c[1]), "+f"(c[2]), "+f"(c[3])
        : "r"(a[0]), "r"(a[1]), "r"(a[2]), "r"(a[3]), "r"(b[0]), "r"(b[1]));
}
__device__ __forceinline__ uint32_t f2bf2(float x, float y) {
    __nv_bfloat162 h = __floats2bfloat162_rn(x, y);
    return *reinterpret_cast<uint32_t*>(&h);
}

// ---------------------------------------------------------------------------
// Selection key packing
// ---------------------------------------------------------------------------
__device__ __forceinline__ unsigned long long pack_key(float s, int idx) {
    unsigned u = __float_as_uint(s);
    u = (u & 0x80000000u) ? ~u : (u | 0x80000000u);
    return ((unsigned long long)u << 32) | (unsigned)idx;
}
__device__ __forceinline__ float unpack_score(unsigned long long key) {
    unsigned u = (unsigned)(key >> 32);
    u = (u & 0x80000000u) ? (u & 0x7fffffffu) : ~u;
    return __uint_as_float(u);
}
__device__ __forceinline__ unsigned long long warp_min_ull(unsigned long long v) {
#pragma unroll
    for (int off = 16; off > 0; off >>= 1) {
        unsigned long long o = __shfl_xor_sync(0xffffffffu, v, off);
        v = (o < v) ? o : v;
    }
    return v;
}

// ---------------------------------------------------------------------------
// Kernel 1: query fp32 -> bf16 convert (tiny). One warp per row.
// ---------------------------------------------------------------------------
__global__ void qconvert_kernel(const float* __restrict__ src,
                                __nv_bfloat16* __restrict__ dst, int rows) {
    int warp = (blockIdx.x * blockDim.x + threadIdx.x) >> 5;
    int lane = threadIdx.x & 31;
    if (warp >= rows) return;
    const float4* srow = reinterpret_cast<const float4*>(src + (size_t)warp * C_DIM);
    uint32_t* drow = reinterpret_cast<uint32_t*>(dst + (size_t)warp * C_DIM);
#pragma unroll
    for (int i = 0; i < C_DIM / 128; i++) {
        int j = i * 32 + lane;
        float4 v = srow[j];
        drow[2 * j]     = f2bf2(v.x, v.y);
        drow[2 * j + 1] = f2bf2(v.z, v.w);
    }
}

// ---------------------------------------------------------------------------
// Kernel 2: fused bf16 GEMM. Bank is read as fp32 and converted in-kernel;
// per-row squared norms accumulated alongside. Two epilogue modes:
//   mode 0 (sample): write scores to g_sample [B x SAMPLE_N]
//   mode 1 (filter): append keys with score <= g_thresh[q] to g_list
// ---------------------------------------------------------------------------
#define BM   128
#define BN   128
#define BKC  64                       // K elems per chunk
#define NCH  (C_DIM / BKC)            // 16
#define A_TILE    16384               // 128 x 64 bf16 (SW128)
#define BF32_TILE 32768               // 128 x 64 fp32 (unit-XOR layout)
#define BBF_TILE  16384               // 128 x 64 bf16 (SW128)
#define OFF_A     0
#define OFF_BF32  (2 * A_TILE)        // 32768
#define OFF_BBF   (OFF_BF32 + BF32_TILE)  // 65536
#define OFF_PART  (OFF_BBF + BBF_TILE)    // 81920 (256 floats)
#define OFF_NORM  (OFF_PART + 1024)       // 82944 (128 floats)
#define GEMM_SMEM (OFF_NORM + 512)        // 83456

__global__ __launch_bounds__(256, 2)
void mma_gemm_kernel(const float* __restrict__ Bank, int M, int mode) {
    extern __shared__ char smem[];
    const uint32_t sb = smem_to_u32(smem);
    const int tid  = threadIdx.x;
    const int wid  = tid >> 5;
    const int lane = tid & 31;
    const int qt = blockIdx.x;            // 0..1 (fast dim -> L2 reuse of bank)
    const int bn = blockIdx.y * BN;
    const int warp_m = wid & 1;
    const int warp_n = wid >> 1;

    const __nv_bfloat16* Abase = g_q_bf + (size_t)qt * BM * C_DIM;

    auto issue_A = [&](int c, int buf) {
        int k0 = c * BKC;
        uint32_t As = sb + OFF_A + buf * A_TILE;
#pragma unroll
        for (int l = 0; l < 4; l++) {
            int id = tid + l * 256;       // 0..1023
            int r  = id >> 3;
            int u  = id & 7;
            uint32_t so = SMEM_SWIZZLE_128B((uint32_t)(r * 128 + u * 16));
            cp_async16(As + so, Abase + (size_t)r * C_DIM + k0 + u * 8, 16);
        }
    };
    auto issue_B = [&](int c) {
        int k0 = c * BKC;                 // float offset
#pragma unroll
        for (int l = 0; l < 8; l++) {
            int id = tid + l * 256;       // 0..2047 16B units
            int r  = id >> 4;             // row 0..127
            int u  = id & 15;             // 16B unit (4 floats)
            int n  = bn + r;
            uint32_t up  = (uint32_t)(u ^ (r & 15));   // XOR layout vs banks
            uint32_t dst = sb + OFF_BF32 + (uint32_t)(r * 256) + up * 16;
            const void* src = Bank + (size_t)(n < M ? n : 0) * C_DIM + k0 + u * 4;
            cp_async16(dst, src, n < M ? 16 : 0);
        }
    };

    float acc[4][4][4];
#pragma unroll
    for (int mi = 0; mi < 4; mi++)
#pragma unroll
        for (int nj = 0; nj < 4; nj++)
#pragma unroll
            for (int e = 0; e < 4; e++) acc[mi][nj][e] = 0.f;

    float pn = 0.f;                       // partial norm of half-row
    const int convr = tid >> 1;           // row owned for conversion
    const int convh = tid & 1;            // half (32 floats)

    issue_A(0, 0);
    issue_B(0);
    cp_commit();

    for (int c = 0; c < NCH; c++) {
        int buf = c & 1;
        cp_wait<0>();
        __syncthreads();

        // ---- convert fp32 tile -> bf16 SW128 tile, accumulate norms ----
        {
            const char* f32b = smem + OFF_BF32 + convr * 256;
#pragma unroll
            for (int j = 0; j < 4; j++) {          // pairs of 16B units
                int u0 = convh * 8 + 2 * j * 1;    // units 2j, 2j+1 within half
                int ua = convh * 8 + 2 * j;
                int ub = ua + 1;
                float4 va = *reinterpret_cast<const float4*>(
                    f32b + ((ua ^ (convr & 15)) * 16));
                float4 vb = *reinterpret_cast<const float4*>(
                    f32b + ((ub ^ (convr & 15)) * 16));
                pn += va.x * va.x + va.y * va.y + va.z * va.z + va.w * va.w;
                pn += vb.x * vb.x + vb.y * vb.y + vb.z * vb.z + vb.w * vb.w;
                uint4 pk;
                pk.x = f2bf2(va.x, va.y);
                pk.y = f2bf2(va.z, va.w);
                pk.z = f2bf2(vb.x, vb.y);
                pk.w = f2bf2(vb.z, vb.w);
                uint32_t so = SMEM_SWIZZLE_128B(
                    (uint32_t)(convr * 128 + convh * 64 + j * 16));
                *reinterpret_cast<uint4*>(smem + OFF_BBF + so) = pk;
                (void)u0;
            }
        }
        __syncthreads();

        if (c + 1 < NCH) {
            issue_A(c + 1, buf ^ 1);
            issue_B(c + 1);
            cp_commit();
        }

        // ---- mma over A[buf] and the bf16 B tile ----
        uint32_t As = sb + OFF_A + buf * A_TILE;
        uint32_t Bs = sb + OFF_BBF;
#pragma unroll
        for (int ks = 0; ks < BKC / 16; ks++) {
            uint32_t a[4][4];
            int arow = warp_m * 64 + (lane & 15);
            int akb  = ks * 16 + (lane >> 4) * 8;
#pragma unroll
            for (int mi = 0; mi < 4; mi++) {
                uint32_t so = SMEM_SWIZZLE_128B(
                    (uint32_t)((arow + mi * 16) * 128 + akb * 2));
                ldmx4(a[mi][0], a[mi][1], a[mi][2], a[mi][3], As + so);
            }
            uint32_t b[4][2];
            int g = lane >> 3;
#pragma unroll
            for (int pair = 0; pair < 2; pair++) {
                int brow = warp_n * 32 + pair * 16 + ((g >> 1) & 1) * 8 + (lane & 7);
                int bkb  = ks * 16 + (g & 1) * 8;
                uint32_t so = SMEM_SWIZZLE_128B((uint32_t)(brow * 128 + bkb * 2));
                uint32_t r0, r1, r2, r3;
                ldmx4(r0, r1, r2, r3, Bs + so);
                b[2 * pair][0] = r0; b[2 * pair][1] = r1;
                b[2 * pair + 1][0] = r2; b[2 * pair + 1][1] = r3;
            }
#pragma unroll
            for (int mi = 0; mi < 4; mi++)
#pragma unroll
                for (int nj = 0; nj < 4; nj++)
                    mma16816(acc[mi][nj], a[mi], b[nj]);
        }
        __syncthreads();
    }

    // ---- finalize per-row norms in smem ----
    float* part  = reinterpret_cast<float*>(smem + OFF_PART);
    float* snorm = reinterpret_cast<float*>(smem + OFF_NORM);
    part[tid] = pn;
    __syncthreads();
    if (tid < 128) snorm[tid] = part[2 * tid] + part[2 * tid + 1];
    __syncthreads();

    const int qbase = qt * BM + warp_m * 64;
    const int nbase = bn + warp_n * 32;

    if (mode == 0) {
        // sample epilogue: write scores into g_sample (row stride SAMPLE_N)
#pragma unroll
        for (int mi = 0; mi < 4; mi++) {
            int q0 = qbase + mi * 16 + (lane >> 2);
#pragma unroll
            for (int nj = 0; nj < 4; nj++) {
                int nloc = warp_n * 32 + nj * 8 + (lane & 3) * 2;
                int n0 = bn + nloc;
                float b0 = snorm[nloc], b1 = snorm[nloc + 1];
                float2 v0 = make_float2(b0 - 2.f * acc[mi][nj][0],
                                        b1 - 2.f * acc[mi][nj][1]);
                float2 v1 = make_float2(b0 - 2.f * acc[mi][nj][2],
                                        b1 - 2.f * acc[mi][nj][3]);
                *reinterpret_cast<float2*>(g_sample + (size_t)q0 * SAMPLE_N + n0) = v0;
                *reinterpret_cast<float2*>(g_sample + (size_t)(q0 + 8) * SAMPLE_N + n0) = v1;
            }
        }
    } else {
        // filter epilogue: append survivors (score <= per-query threshold)
#pragma unroll
        for (int mi = 0; mi < 4; mi++) {
            int q0 = qbase + mi * 16 + (lane >> 2);
            int q1 = q0 + 8;
            float T0 = g_thresh[q0];
            float T1 = g_thresh[q1];
#pragma unroll
            for (int nj = 0; nj < 4; nj++) {
                int nloc = warp_n * 32 + nj * 8 + (lane & 3) * 2;
                int n0 = bn + nloc;
                if (n0 < M) {
                    float b0 = snorm[nloc];
                    float s00 = b0 - 2.f * acc[mi][nj][0];
                    float s10 = b0 - 2.f * acc[mi][nj][2];
                    if (s00 <= T0) {
                        int pos = atomicAdd(&g_count[q0], 1);
                        if (pos < CAP) g_list[(size_t)q0 * CAP + pos] = pack_key(s00, n0);
                    }
                    if (s10 <= T1) {
                        int pos = atomicAdd(&g_count[q1], 1);
                        if (pos < CAP) g_list[(size_t)q1 * CAP + pos] = pack_key(s10, n0);
                    }
                    if (n0 + 1 < M) {
                        float b1 = snorm[nloc + 1];
                        float s01 = b1 - 2.f * acc[mi][nj][1];
                        float s11 = b1 - 2.f * acc[mi][nj][3];
                        if (s01 <= T0) {
                            int pos = atomicAdd(&g_count[q0], 1);
                            if (pos < CAP) g_list[(size_t)q0 * CAP + pos] = pack_key(s01, n0 + 1);
                        }
                        if (s11 <= T1) {
                            int pos = atomicAdd(&g_count[q1], 1);
                            if (pos < CAP) g_list[(size_t)q1 * CAP + pos] = pack_key(s11, n0 + 1);
                        }
                    }
                }
            }
        }
    }
}

// ---------------------------------------------------------------------------
// Kernel 3: per-query threshold = THR_RANK-th smallest of the sample row.
// ---------------------------------------------------------------------------
__global__ __launch_bounds__(256)
void sample_thresh_kernel() {
    const int q    = blockIdx.x;
    const int tid  = threadIdx.x;
    const int wid  = tid >> 5;
    const int lane = tid & 31;
    const float4* row4 = reinterpret_cast<const float4*>(g_sample + (size_t)q * SAMPLE_N);
    const int N4 = SAMPLE_N / 4;             // 832
    __shared__ unsigned long long wkeys[64];

    float ls[THR_RANK];
#pragma unroll
    for (int j = 0; j < THR_RANK; j++) ls[j] = FLT_MAX;
    const int per_warp = (N4 + 7) / 8;       // 104
    const int j0 = wid * per_warp;
    const int j1 = min(N4, j0 + per_warp);
    for (int j4 = j0 + lane; j4 < j1; j4 += 32) {
        float4 v = row4[j4];
        float e[4] = {v.x, v.y, v.z, v.w};
#pragma unroll
        for (int t = 0; t < 4; t++) {
            float cs = e[t];
            if (cs < ls[THR_RANK - 1]) {
#pragma unroll
                for (int j = 0; j < THR_RANK; j++) {
                    if (cs < ls[j]) { float ts = ls[j]; ls[j] = cs; cs = ts; }
                }
            }
        }
    }
    unsigned long long kk[THR_RANK];
#pragma unroll
    for (int j = 0; j < THR_RANK; j++) kk[j] = pack_key(ls[j], (wid << 8) | (lane << 3) | j);
    unsigned long long mine = ~0ull;
#pragma unroll
    for (int r = 0; r < THR_RANK; r++) {
        unsigned long long best = warp_min_ull(kk[0]);
        if (kk[0] == best) {
#pragma unroll
            for (int j = 0; j < THR_RANK - 1; j++) kk[j] = kk[j + 1];
            kk[THR_RANK - 1] = ~0ull;
        }
        if (lane == r) mine = best;
    }
    if (lane < THR_RANK) wkeys[wid * THR_RANK + lane] = mine;
    __syncthreads();

    if (wid == 0) {
        unsigned long long p0 = wkeys[lane], p1 = wkeys[32 + lane];
        if (p1 < p0) { unsigned long long t = p0; p0 = p1; p1 = t; }
        unsigned long long best = 0;
#pragma unroll
        for (int r = 0; r < THR_RANK; r++) {
            best = warp_min_ull(p0);
            if (p0 == best) { p0 = p1; p1 = ~0ull; }
        }
        if (lane == 0) {
            g_thresh[q] = unpack_score(best);
            g_count[q]  = 0;
        }
    }
}

// ---------------------------------------------------------------------------
// Kernel 4: per-query exact top-64 of the filtered keys.
// ---------------------------------------------------------------------------
__global__ __launch_bounds__(256)
void merge_cand_kernel() {
    const int q    = blockIdx.x;
    const int tid  = threadIdx.x;
    const int wid  = tid >> 5;
    const int lane = tid & 31;
    const int n    = min(g_count[q], CAP);
    const unsigned long long* list = g_list + (size_t)q * CAP;
    __shared__ unsigned long long keys[256];

    unsigned long long kk[8];
#pragma unroll
    for (int j = 0; j < 8; j++) kk[j] = ~0ull;
    for (int t = tid; t < n; t += 256) {
        unsigned long long ck = list[t];
        if (ck < kk[7]) {
#pragma unroll
            for (int j = 0; j < 8; j++) {
                if (ck < kk[j]) { unsigned long long tk = kk[j]; kk[j] = ck; ck = tk; }
            }
        }
    }

    unsigned long long mine = ~0ull;
#pragma unroll
    for (int r = 0; r < 32; r++) {
        unsigned long long best = warp_min_ull(kk[0]);
        if (kk[0] == best && best != ~0ull) {
#pragma unroll
            for (int j = 0; j < 7; j++) kk[j] = kk[j + 1];
            kk[7] = ~0ull;
        }
        if (lane == r) mine = best;
    }
    keys[wid * 32 + lane] = mine;
    __syncthreads();

    for (int k = 2; k <= 256; k <<= 1) {
        for (int j = k >> 1; j > 0; j >>= 1) {
            int ixj = tid ^ j;
            if (ixj > tid) {
                unsigned long long a = keys[tid], b = keys[ixj];
                bool up = ((tid & k) == 0);
                if ((a > b) == up) { keys[tid] = b; keys[ixj] = a; }
            }
            __syncthreads();
        }
    }
    if (tid < NCAND) {
        unsigned long long kv = keys[tid];
        g_cand[q * NCAND + tid] = (kv == ~0ull) ? 0 : (int)(kv & 0xffffffffu);
    }
}

// ---------------------------------------------------------------------------
// Kernel 5: exact fp32 rescore (dot + norm inline), top-16, gather.
// ---------------------------------------------------------------------------
__global__ __launch_bounds__(256)
void rescore_gather_kernel(const float* __restrict__ Q,
                           const float* __restrict__ Bank,
                           const float* __restrict__ traj,
                           float* __restrict__ out, int TD) {
    const int q   = blockIdx.x;
    const int tid = threadIdx.x;
    const int wid = tid >> 5, lane = tid & 31;

    __shared__ __align__(16) float qrow[C_DIM];
    __shared__ float cs[NCAND];
    __shared__ int   ci[NCAND];
    __shared__ unsigned long long k64[NCAND];

    for (int t = tid; t < C_DIM; t += 256)
        qrow[t] = Q[(size_t)q * C_DIM + t];
    __syncthreads();

    const float4* q4 = reinterpret_cast<const float4*>(qrow);
    for (int cand = wid; cand < NCAND; cand += 8) {
        int idx = g_cand[q * NCAND + cand];
        const float4* b4 = reinterpret_cast<const float4*>(Bank + (size_t)idx * C_DIM);
        float acc = 0.f, nsq = 0.f;
#pragma unroll
        for (int j = lane; j < C_DIM / 4; j += 32) {
            float4 a = q4[j], b = b4[j];
            acc += a.x * b.x + a.y * b.y + a.z * b.z + a.w * b.w;
            nsq += b.x * b.x + b.y * b.y + b.z * b.z + b.w * b.w;
        }
#pragma unroll
        for (int off = 16; off > 0; off >>= 1) {
            acc += __shfl_xor_sync(0xffffffffu, acc, off);
            nsq += __shfl_xor_sync(0xffffffffu, nsq, off);
        }
        if (lane == 0) { cs[cand] = nsq - 2.0f * acc; ci[cand] = idx; }
    }
    __syncthreads();

    if (tid < NCAND) k64[tid] = pack_key(cs[tid], ci[tid]);
    __syncthreads();
    for (int k = 2; k <= NCAND; k <<= 1) {
        for (int j = k >> 1; j > 0; j >>= 1) {
            for (int t = tid; t < NCAND; t += 256) {
                int ixj = t ^ j;
                if (ixj > t) {
                    unsigned long long a = k64[t], b = k64[ixj];
                    bool up = ((t & k) == 0);
                    if ((a > b) == up) { k64[t] = b; k64[ixj] = a; }
                }
            }
            __syncthreads();
        }
    }

    for (int t = tid; t < KSEL * TD; t += 256) {
        int r = t / TD;
        int c = t - r * TD;
        int idx = (int)(k64[r] & 0xffffffffu);
        out[(size_t)q * KSEL * TD + t] = traj[(size_t)idx * TD + c];
    }
}

// ---------------------------------------------------------------------------
// Launch
// ---------------------------------------------------------------------------
extern "C" void kernel_launch(void* const* d_in, const int* in_sizes, int n_in,
                              void* d_out, int out_size) {
    const float* Q    = (const float*)d_in[0];
    const float* Bank = (const float*)d_in[1];
    const float* Traj = (const float*)d_in[2];
    float* out = (float*)d_out;

    const int C  = C_DIM;
    const int B  = in_sizes[0] / C;    // 256
    const int M  = in_sizes[1] / C;    // 200000
    const int TD = in_sizes[2] / M;    // 24

    cudaFuncSetAttribute(mma_gemm_kernel,
                         cudaFuncAttributeMaxDynamicSharedMemorySize, GEMM_SMEM);

    __nv_bfloat16* qbf_p = nullptr;
    cudaGetSymbolAddress((void**)&qbf_p, g_q_bf);

    // 1) convert query to bf16 (tiny)
    {
        int qctas = (B * 32 + 255) / 256;
        qconvert_kernel<<<qctas, 256>>>(Q, qbf_p, B);
    }
    // 2) sample mini-GEMM over first SAMPLE_N bank rows (fused convert+norm)
    {
        dim3 grid(B / BM, SAMPLE_TILES);
        mma_gemm_kernel<<<grid, 256, GEMM_SMEM>>>(Bank, M, 0);
    }
    // 3) per-query threshold + counter reset
    sample_thresh_kernel<<<B, 256>>>();
    // 4) main fused GEMM with threshold-filter epilogue
    {
        dim3 grid(B / BM, (M + BN - 1) / BN);
        mma_gemm_kernel<<<grid, 256, GEMM_SMEM>>>(Bank, M, 1);
    }
    // 5) exact top-64 of filtered keys
    merge_cand_kernel<<<B, 256>>>();
    // 6) exact fp32 rescore + top-16 + gather
    rescore_gather_kernel<<<B, 256>>>(Q, Bank, Traj, out, TD);
}